// round 3
// baseline (speedup 1.0000x reference)
#include <cuda_runtime.h>
#include <cuda_fp16.h>
#include <math.h>
#include <stdint.h>

// Problem constants
#define E_DIM   256
#define NA      900
#define BS      2
#define NCAM    6
#define NLVL    4
#define NPTS    13
#define NG      8
#define NANCH   (BS*NA)          // 1800
#define WO      416              // G*NL*NPTS = 8*4*13
#define NSAMP   (NCAM*NLVL*NPTS) // 312
#define SOFTN   312              // softmax length per group

// Feature-map level shapes:  0: 64x176  1: 32x88  2: 16x44  3: 8x22

// -------- device scratch (no runtime allocation allowed) --------
__device__ __half g_fmt0[34603008];   // [12][64*176][256] fp16
__device__ __half g_fmt1[8650752];    // [12][32*88][256]
__device__ __half g_fmt2[2162688];    // [12][16*44][256]
__device__ __half g_fmt3[540672];     // [12][8*22][256]
__device__ float  g_featW[NANCH*WO];  // (feat+anchor_embed) @ wfc_w   (no bias)
__device__ float  g_ceWb[12*WO];      // ce @ wfc_w + wfc_b
__device__ float  g_fused[NANCH*E_DIM];

__constant__ float c_fix[7][3] = {
  {0.f,0.f,0.f},{0.45f,0.f,0.f},{-0.45f,0.f,0.f},{0.f,0.45f,0.f},
  {0.f,-0.45f,0.f},{0.f,0.f,0.45f},{0.f,0.f,-0.45f}};

// ------- transpose+convert [b,c,E,H,W] f32 -> [b,c,H,W,E] f16 -------
// tile: 64 E-rows x 32 HW-cols.  block (32,8)
__global__ void transpose_kernel(const float* __restrict__ src, int level){
  __half* dst; int HW;
  if(level==0){dst=g_fmt0; HW=11264;} else if(level==1){dst=g_fmt1; HW=2816;}
  else if(level==2){dst=g_fmt2; HW=704;} else {dst=g_fmt3; HW=176;}
  __shared__ float tile[64][33];
  int img = blockIdx.z;
  const float* s = src + (size_t)img * E_DIM * HW;
  __half* d      = dst + (size_t)img * HW * E_DIM;
  int hw0 = blockIdx.x*32, e0 = blockIdx.y*64;
  int tx = threadIdx.x, ty = threadIdx.y;
  int hw = hw0+tx;
  #pragma unroll
  for(int i=ty;i<64;i+=8){
    tile[i][tx] = (hw<HW) ? s[(size_t)(e0+i)*HW + hw] : 0.f;
  }
  __syncthreads();
  #pragma unroll
  for(int i=ty;i<32;i+=8){
    int hwi = hw0+i;
    if(hwi<HW){
      __half2 v = __floats2half2_rn(tile[2*tx][i], tile[2*tx+1][i]);
      *(__half2*)(d + (size_t)hwi*E_DIM + e0 + 2*tx) = v;
    }
  }
}

// ---------------- camera embed ----------------
__device__ __forceinline__ float blockSum256(float v, float* red){
  int tid = threadIdx.x;
  red[tid] = v; __syncthreads();
  #pragma unroll
  for(int s=128;s>0;s>>=1){
    if(tid<s) red[tid]+=red[tid+s];
    __syncthreads();
  }
  float r = red[0]; __syncthreads();
  return r;
}

__global__ void cam_embed_kernel(const float* __restrict__ pm,
    const float* __restrict__ ce1w, const float* __restrict__ ce1b,
    const float* __restrict__ ln1g, const float* __restrict__ ln1b,
    const float* __restrict__ ce2w, const float* __restrict__ ce2b,
    const float* __restrict__ ln2g, const float* __restrict__ ln2b,
    const float* __restrict__ wfcw, const float* __restrict__ wfcb){
  int img = blockIdx.x;          // b*6+c, 12 blocks
  int tid = threadIdx.x;         // 256
  __shared__ float cam[12];
  __shared__ float h[E_DIM];
  __shared__ float red[E_DIM];
  if(tid<12) cam[tid] = pm[img*16 + tid];
  __syncthreads();
  float v = ce1b[tid];
  #pragma unroll
  for(int i=0;i<12;i++) v += cam[i]*ce1w[i*E_DIM+tid];
  v = fmaxf(v,0.f);
  float m = blockSum256(v, red) * (1.f/E_DIM);
  float dvar = v - m;
  float var = blockSum256(dvar*dvar, red) * (1.f/E_DIM);
  v = dvar * rsqrtf(var + 1e-5f) * ln1g[tid] + ln1b[tid];
  h[tid] = v; __syncthreads();
  float v2 = ce2b[tid];
  for(int i=0;i<E_DIM;i++) v2 += h[i]*ce2w[i*E_DIM+tid];
  v2 = fmaxf(v2,0.f);
  __syncthreads();
  float m2 = blockSum256(v2, red) * (1.f/E_DIM);
  float d2 = v2 - m2;
  float var2 = blockSum256(d2*d2, red) * (1.f/E_DIM);
  v2 = d2 * rsqrtf(var2 + 1e-5f) * ln2g[tid] + ln2b[tid];
  h[tid] = v2; __syncthreads();
  for(int o=tid;o<WO;o+=256){
    float a = wfcb[o];
    for(int e=0;e<E_DIM;e++) a += h[e]*wfcw[e*WO+o];
    g_ceWb[img*WO+o] = a;
  }
}

// ---------------- featW = (instance_feature + anchor_embed) @ wfc_w ----------------
__global__ __launch_bounds__(256) void featw_kernel(const float* __restrict__ iff,
    const float* __restrict__ ae, const float* __restrict__ wfcw){
  __shared__ float fs[32][E_DIM];
  int a0 = blockIdx.x*32;
  int tid = threadIdx.x;
  #pragma unroll 4
  for(int m=0;m<32;m++){
    int a = a0+m;
    fs[m][tid] = (a<NANCH) ? (iff[(size_t)a*E_DIM+tid] + ae[(size_t)a*E_DIM+tid]) : 0.f;
  }
  __syncthreads();
  for(int o=tid;o<WO;o+=256){
    float acc[32];
    #pragma unroll
    for(int m=0;m<32;m++) acc[m]=0.f;
    for(int e=0;e<E_DIM;e++){
      float wv = wfcw[e*WO+o];
      #pragma unroll
      for(int m=0;m<32;m++) acc[m] += fs[m][e]*wv;
    }
    #pragma unroll
    for(int m=0;m<32;m++){
      int a = a0+m;
      if(a<NANCH) g_featW[(size_t)a*WO+o] = acc[m];
    }
  }
}

// ---------------- main: keypoints + softmax weights + deformable gather ----------------
__global__ __launch_bounds__(256) void dfa_main_kernel(
    const float* __restrict__ iff, const float* __restrict__ anc,
    const float* __restrict__ pm, const float* __restrict__ wh,
    const float* __restrict__ lfcw, const float* __restrict__ lfcb,
    float* __restrict__ out){
  int n = blockIdx.x;                 // global anchor 0..1799
  int b = n / NA;
  int tid = threadIdx.x;
  int wid = tid>>5, ln = tid&31;

  __shared__ float sIF[E_DIM];
  __shared__ float sA[11];
  __shared__ float sLS[18];
  __shared__ float sKP[NPTS][3];
  __shared__ float sGU[NCAM*NPTS], sGV[NCAM*NPTS];
  __shared__ float sWgt[NCAM*WO];     // logits -> softmaxed weights, [c][l][p][g]
  __shared__ float sFused[E_DIM];

  // phase 1: loads + init
  sIF[tid] = iff[(size_t)n*E_DIM+tid];
  sFused[tid] = 0.f;
  if(tid<11) sA[tid] = anc[(size_t)n*11+tid];
  __syncthreads();

  // phase 2: learned scales + logits
  if(tid<18){
    float v = lfcb[tid];
    for(int e=0;e<E_DIM;e++) v += sIF[e]*lfcw[e*18+tid];
    sLS[tid] = 1.f/(1.f+__expf(-v)) - 0.5f;
  }
  #pragma unroll
  for(int idx=tid; idx<NCAM*WO; idx+=256){
    int c = idx/WO, o = idx - c*WO;
    sWgt[idx] = g_featW[(size_t)n*WO+o] + g_ceWb[(b*NCAM+c)*WO+o];
  }
  __syncthreads();

  // phase 3: keypoints (lanes 0..12) + softmax per group (warp g)
  if(tid<NPTS){
    float sx = expf(sA[3]), sy2 = expf(sA[4]), sz = expf(sA[5]);
    float kx,ky,kz;
    if(tid<7){ kx=c_fix[tid][0]*sx; ky=c_fix[tid][1]*sy2; kz=c_fix[tid][2]*sz; }
    else { int i=tid-7; kx=sLS[i*3+0]*sx; ky=sLS[i*3+1]*sy2; kz=sLS[i*3+2]*sz; }
    float sn = sA[6], cs = sA[7];
    sKP[tid][0] = cs*kx - sn*ky + sA[0];
    sKP[tid][1] = sn*kx + cs*ky + sA[1];
    sKP[tid][2] = kz + sA[2];
  }
  {
    int g = wid;
    float mx = -1e30f;
    for(int j=ln;j<SOFTN;j+=32){
      int c=j/52, k=j-c*52;
      mx = fmaxf(mx, sWgt[c*WO + k*8 + g]);
    }
    #pragma unroll
    for(int o=16;o;o>>=1) mx = fmaxf(mx, __shfl_xor_sync(0xffffffffu, mx, o));
    float sum = 0.f;
    for(int j=ln;j<SOFTN;j+=32){
      int c=j/52, k=j-c*52;
      sum += __expf(sWgt[c*WO + k*8 + g] - mx);
    }
    #pragma unroll
    for(int o=16;o;o>>=1) sum += __shfl_xor_sync(0xffffffffu, sum, o);
    float inv = 1.f/sum;
    for(int j=ln;j<SOFTN;j+=32){
      int c=j/52, k=j-c*52;
      int idx = c*WO + k*8 + g;
      sWgt[idx] = __expf(sWgt[idx] - mx) * inv;
    }
  }
  __syncthreads();

  // phase 4: projection (78 threads: c*13+p)
  if(tid < NCAM*NPTS){
    int c = tid/NPTS, p = tid - c*NPTS;
    const float* P = pm + (size_t)(b*NCAM+c)*16;
    float X = sKP[p][0], Y = sKP[p][1], Z = sKP[p][2];
    float r0 = P[0]*X + P[1]*Y + P[2]*Z  + P[3];
    float r1 = P[4]*X + P[5]*Y + P[6]*Z  + P[7];
    float r2 = P[8]*X + P[9]*Y + P[10]*Z + P[11];
    float z = fmaxf(r2, 1e-5f);
    float iwx = wh[(b*NCAM+c)*2+0], iwy = wh[(b*NCAM+c)*2+1];
    sGU[tid] = (r0/z)/iwx*2.f - 1.f;
    sGV[tid] = (r1/z)/iwy*2.f - 1.f;
  }
  __syncthreads();

  // phase 5: sampling.  warp w owns samples s = w, w+8, ...
  // Lane ln owns channels [8*ln .. 8*ln+7]  (all in group ln>>2) -> one weight/sample
  float acc[8];
  #pragma unroll
  for(int j=0;j<8;j++) acc[j]=0.f;
  int g = ln>>2;

  for(int s = wid; s < NSAMP; s += 8){
    int c = s/52, r = s - c*52, l = r/13, p = r - l*13;
    const __half* fml; int Wl, Hl;
    if(l==0){ fml=g_fmt0; Wl=176; Hl=64; }
    else if(l==1){ fml=g_fmt1; Wl=88; Hl=32; }
    else if(l==2){ fml=g_fmt2; Wl=44; Hl=16; }
    else { fml=g_fmt3; Wl=22; Hl=8; }
    float fW = (float)Wl, fH = (float)Hl;
    float gu = sGU[c*NPTS+p], gv = sGV[c*NPTS+p];
    float gx = (gu+1.f)*(fW*0.5f) - 0.5f;
    float gy = (gv+1.f)*(fH*0.5f) - 0.5f;
    if(!(gx > -1.f && gx < fW && gy > -1.f && gy < fH)) continue;
    float x0f = floorf(gx), y0f = floorf(gy);
    float wx1 = gx - x0f, wy1 = gy - y0f;
    float wx0 = 1.f - wx1, wy0 = 1.f - wy1;
    int x0 = (int)x0f, y0 = (int)y0f;
    bool vx0 = (x0 >= 0), vx1 = (x0+1 < Wl);
    bool vy0 = (y0 >= 0), vy1 = (y0+1 < Hl);
    const __half* imgb = fml + (size_t)(b*NCAM+c)*Hl*Wl*E_DIM;
    float sv[8];
    #pragma unroll
    for(int j=0;j<8;j++) sv[j]=0.f;
    #define TAP(px, py, wt) { \
      uint4 u = *((const uint4*)(imgb + ((size_t)(py)*Wl + (px))*E_DIM) + ln); \
      const __half2* hp = (const __half2*)&u; \
      _Pragma("unroll") \
      for(int j=0;j<4;j++){ \
        float2 f = __half22float2(hp[j]); \
        sv[2*j]   += (wt)*f.x; \
        sv[2*j+1] += (wt)*f.y; \
      } }
    if(vy0){
      if(vx0) TAP(x0,   y0, wx0*wy0);
      if(vx1) TAP(x0+1, y0, wx1*wy0);
    }
    if(vy1){
      if(vx0) TAP(x0,   y0+1, wx0*wy1);
      if(vx1) TAP(x0+1, y0+1, wx1*wy1);
    }
    #undef TAP
    float wt = sWgt[s*8 + g];
    #pragma unroll
    for(int j=0;j<8;j++) acc[j] += wt*sv[j];
  }
  #pragma unroll
  for(int j=0;j<8;j++) atomicAdd(&sFused[8*ln+j], acc[j]);
  __syncthreads();

  g_fused[(size_t)n*E_DIM + tid] = sFused[tid];
  out[(size_t)n*512 + 256 + tid] = sIF[tid];   // concat tail
}

// ---------------- final projection: out[:, :256] = fused @ op_w + op_b ----------------
__global__ __launch_bounds__(256) void outproj_kernel(const float* __restrict__ opw,
    const float* __restrict__ opb, float* __restrict__ out){
  __shared__ float fs[32][E_DIM];
  int a0 = blockIdx.x*32;
  int tid = threadIdx.x;
  #pragma unroll 4
  for(int m=0;m<32;m++){
    int a = a0+m;
    fs[m][tid] = (a<NANCH) ? g_fused[(size_t)a*E_DIM+tid] : 0.f;
  }
  __syncthreads();
  float acc[32];
  float bias = opb[tid];
  #pragma unroll
  for(int m=0;m<32;m++) acc[m]=bias;
  for(int e=0;e<E_DIM;e++){
    float wv = opw[e*E_DIM+tid];
    #pragma unroll
    for(int m=0;m<32;m++) acc[m] += fs[m][e]*wv;
  }
  #pragma unroll
  for(int m=0;m<32;m++){
    int a = a0+m;
    if(a<NANCH) out[(size_t)a*512 + tid] = acc[m];
  }
}

// ---------------- host launcher ----------------
extern "C" void kernel_launch(void* const* d_in, const int* in_sizes, int n_in,
                              void* d_out, int out_size) {
  int iIF=0, iAE=2, iPM, iWH, iFM0, iFM1, iFM2, iFM3;
  int iANC=1;
  if(in_sizes[3]==192){ iPM=3; iWH=4; iFM0=5; iFM1=6; iFM2=7; iFM3=8; }
  else                { iFM0=3; iFM1=4; iFM2=5; iFM3=6; iPM=7; iWH=8; }
  int iLFW=9, iLFB=10, iC1W=11, iC1B=12, iL1G=13, iL1B=14,
      iC2W=15, iC2B=16, iL2G=17, iL2B=18, iWFW=19, iWFB=20, iOPW=21, iOPB=22;

  const float* iff  = (const float*)d_in[iIF];
  const float* anc  = (const float*)d_in[iANC];
  const float* ae   = (const float*)d_in[iAE];
  const float* pm   = (const float*)d_in[iPM];
  const float* wh   = (const float*)d_in[iWH];
  const float* fm0  = (const float*)d_in[iFM0];
  const float* fm1  = (const float*)d_in[iFM1];
  const float* fm2  = (const float*)d_in[iFM2];
  const float* fm3  = (const float*)d_in[iFM3];
  const float* lfcw = (const float*)d_in[iLFW];
  const float* lfcb = (const float*)d_in[iLFB];
  const float* c1w  = (const float*)d_in[iC1W];
  const float* c1b  = (const float*)d_in[iC1B];
  const float* l1g  = (const float*)d_in[iL1G];
  const float* l1b  = (const float*)d_in[iL1B];
  const float* c2w  = (const float*)d_in[iC2W];
  const float* c2b  = (const float*)d_in[iC2B];
  const float* l2g  = (const float*)d_in[iL2G];
  const float* l2b  = (const float*)d_in[iL2B];
  const float* wfw  = (const float*)d_in[iWFW];
  const float* wfb  = (const float*)d_in[iWFB];
  const float* opw  = (const float*)d_in[iOPW];
  const float* opb  = (const float*)d_in[iOPB];
  float* out = (float*)d_out;

  dim3 tb(32,8,1);
  transpose_kernel<<<dim3(352,4,12), tb>>>(fm0, 0);
  transpose_kernel<<<dim3( 88,4,12), tb>>>(fm1, 1);
  transpose_kernel<<<dim3( 22,4,12), tb>>>(fm2, 2);
  transpose_kernel<<<dim3(  6,4,12), tb>>>(fm3, 3);

  cam_embed_kernel<<<12, 256>>>(pm, c1w, c1b, l1g, l1b, c2w, c2b, l2g, l2b, wfw, wfb);
  featw_kernel<<<(NANCH+31)/32, 256>>>(iff, ae, wfw);
  dfa_main_kernel<<<NANCH, 256>>>(iff, anc, pm, wh, lfcw, lfcb, out);
  outproj_kernel<<<(NANCH+31)/32, 256>>>(opw, opb, out);
}

// round 4
// speedup vs baseline: 1.2925x; 1.2925x over previous
#include <cuda_runtime.h>
#include <cuda_fp16.h>
#include <math.h>
#include <stdint.h>

// Problem constants
#define E_DIM   256
#define NA      900
#define BS      2
#define NCAM    6
#define NLVL    4
#define NPTS    13
#define NG      8
#define NANCH   (BS*NA)          // 1800
#define WO      416              // G*NL*NPTS
#define NSAMP   (NCAM*NLVL*NPTS) // 312
#define SOFTN   312

// Levels: 0: 64x176  1: 32x88  2: 16x44  3: 8x22
// Unified fp16 feature buffer offsets (in halves):
//  l0: 0            size 12*11264*256 = 34603008
//  l1: 34603008     size 12*2816*256  =  8650752
//  l2: 43253760     size 12*704*256   =  2162688
//  l3: 45416448     size 12*176*256   =   540672
#define FMT_TOTAL 45957120

__device__ __half g_fmt[FMT_TOTAL];
__device__ float  g_featW[NANCH*WO];
__device__ float  g_ceWb[12*WO];
__device__ float  g_ls[NANCH*18];
__device__ float  g_fused[NANCH*E_DIM];

__constant__ float c_fix[7][3] = {
  {0.f,0.f,0.f},{0.45f,0.f,0.f},{-0.45f,0.f,0.f},{0.f,0.45f,0.f},
  {0.f,-0.45f,0.f},{0.f,0.f,0.45f},{0.f,0.f,-0.45f}};

__constant__ int c_lW[4]   = {176,88,44,22};
__constant__ int c_lH[4]   = {64,32,16,8};
__constant__ int c_lOff[4] = {0,34603008,43253760,45416448};
__constant__ int c_lStr[4] = {2883584,720896,180224,45056};   // HW*256 per image

// ---------- merged vectorized transpose+convert: [img,E,H,W] f32 -> unified [img,H,W,E] f16 ----------
// tile 64E x 64HW, block 256 threads.
// blocks/level = 12 * 4 * ceil(HW/64):  l0 8448, l1 2112, l2 528, l3 144 -> 11232 total
__global__ __launch_bounds__(256) void transpose_all_kernel(
    const float* __restrict__ f0, const float* __restrict__ f1,
    const float* __restrict__ f2, const float* __restrict__ f3){
  int bid = blockIdx.x;
  int l, bl;
  if(bid < 8448){ l=0; bl=bid; }
  else if(bid < 10560){ l=1; bl=bid-8448; }
  else if(bid < 11088){ l=2; bl=bid-10560; }
  else { l=3; bl=bid-11088; }
  const float* src; int HW, thw; int dstOff;
  if(l==0){src=f0;HW=11264;thw=176;dstOff=0;}
  else if(l==1){src=f1;HW=2816;thw=44;dstOff=34603008;}
  else if(l==2){src=f2;HW=704;thw=11;dstOff=43253760;}
  else {src=f3;HW=176;thw=3;dstOff=45416448;}
  int e_t = bl & 3; int tmp = bl >> 2;
  int hw_t = tmp % thw; int img = tmp / thw;
  int e0 = e_t*64, hw0 = hw_t*64;
  const float* s = src + (size_t)img*E_DIM*HW;
  __half* d = g_fmt + dstOff + (size_t)img*HW*E_DIM;

  __shared__ float sm[64][65];
  int t = threadIdx.x;
  int col = t & 15, row0 = t >> 4;      // col: float4 column (4 hw), row0: 0..15
  int hwc = hw0 + col*4;
  if(hwc < HW){
    #pragma unroll
    for(int i=0;i<4;i++){
      int r = row0 + 16*i;
      float4 v = *(const float4*)(s + (size_t)(e0+r)*HW + hwc);
      sm[r][col*4+0]=v.x; sm[r][col*4+1]=v.y; sm[r][col*4+2]=v.z; sm[r][col*4+3]=v.w;
    }
  }
  __syncthreads();
  int chunk = t & 7, hrow = t >> 3;     // chunk: 8 E values, hrow: 0..31
  #pragma unroll
  for(int i=0;i<2;i++){
    int hw = hrow + 32*i;
    if(hw0+hw < HW){
      __half2 h[4];
      #pragma unroll
      for(int j=0;j<4;j++)
        h[j] = __floats2half2_rn(sm[8*chunk+2*j][hw], sm[8*chunk+2*j+1][hw]);
      *(uint4*)(d + (size_t)(hw0+hw)*E_DIM + e0 + 8*chunk) = *(uint4*)h;
    }
  }
}

// ---------- learned scales: g_ls = sigmoid(iff @ lfc_w + lfc_b) - 0.5 ----------
__global__ __launch_bounds__(256) void ls_kernel(const float* __restrict__ iff,
    const float* __restrict__ lfcw, const float* __restrict__ lfcb){
  int idx = blockIdx.x*256 + threadIdx.x;
  if(idx >= NANCH*18) return;
  int a = idx/18, o = idx - 18*a;
  const float* f = iff + (size_t)a*E_DIM;
  float v = lfcb[o];
  #pragma unroll 4
  for(int e=0;e<E_DIM;e++) v += f[e]*lfcw[e*18+o];
  g_ls[idx] = 1.f/(1.f+__expf(-v)) - 0.5f;
}

// ---------- camera embed ----------
__device__ __forceinline__ float blockSum256(float v, float* red){
  int tid = threadIdx.x;
  red[tid] = v; __syncthreads();
  #pragma unroll
  for(int s=128;s>0;s>>=1){
    if(tid<s) red[tid]+=red[tid+s];
    __syncthreads();
  }
  float r = red[0]; __syncthreads();
  return r;
}

__global__ void cam_embed_kernel(const float* __restrict__ pm,
    const float* __restrict__ ce1w, const float* __restrict__ ce1b,
    const float* __restrict__ ln1g, const float* __restrict__ ln1b,
    const float* __restrict__ ce2w, const float* __restrict__ ce2b,
    const float* __restrict__ ln2g, const float* __restrict__ ln2b,
    const float* __restrict__ wfcw, const float* __restrict__ wfcb){
  int img = blockIdx.x;
  int tid = threadIdx.x;
  __shared__ float cam[12];
  __shared__ float h[E_DIM];
  __shared__ float red[E_DIM];
  if(tid<12) cam[tid] = pm[img*16 + tid];
  __syncthreads();
  float v = ce1b[tid];
  #pragma unroll
  for(int i=0;i<12;i++) v += cam[i]*ce1w[i*E_DIM+tid];
  v = fmaxf(v,0.f);
  float m = blockSum256(v, red) * (1.f/E_DIM);
  float dvar = v - m;
  float var = blockSum256(dvar*dvar, red) * (1.f/E_DIM);
  v = dvar * rsqrtf(var + 1e-5f) * ln1g[tid] + ln1b[tid];
  h[tid] = v; __syncthreads();
  float v2 = ce2b[tid];
  for(int i=0;i<E_DIM;i++) v2 += h[i]*ce2w[i*E_DIM+tid];
  v2 = fmaxf(v2,0.f);
  __syncthreads();
  float m2 = blockSum256(v2, red) * (1.f/E_DIM);
  float d2 = v2 - m2;
  float var2 = blockSum256(d2*d2, red) * (1.f/E_DIM);
  v2 = d2 * rsqrtf(var2 + 1e-5f) * ln2g[tid] + ln2b[tid];
  h[tid] = v2; __syncthreads();
  for(int o=tid;o<WO;o+=256){
    float a = wfcb[o];
    for(int e=0;e<E_DIM;e++) a += h[e]*wfcw[e*WO+o];
    g_ceWb[img*WO+o] = a;
  }
}

// ---------- featW = (iff + anchor_embed) @ wfc_w ----------
__global__ __launch_bounds__(256) void featw_kernel(const float* __restrict__ iff,
    const float* __restrict__ ae, const float* __restrict__ wfcw){
  __shared__ float fs[32][E_DIM];
  int a0 = blockIdx.x*32;
  int tid = threadIdx.x;
  #pragma unroll 4
  for(int m=0;m<32;m++){
    int a = a0+m;
    fs[m][tid] = (a<NANCH) ? (iff[(size_t)a*E_DIM+tid] + ae[(size_t)a*E_DIM+tid]) : 0.f;
  }
  __syncthreads();
  for(int o=tid;o<WO;o+=256){
    float acc[32];
    #pragma unroll
    for(int m=0;m<32;m++) acc[m]=0.f;
    for(int e=0;e<E_DIM;e++){
      float wv = wfcw[e*WO+o];
      #pragma unroll
      for(int m=0;m<32;m++) acc[m] += fs[m][e]*wv;
    }
    #pragma unroll
    for(int m=0;m<32;m++){
      int a = a0+m;
      if(a<NANCH) g_featW[(size_t)a*WO+o] = acc[m];
    }
  }
}

// ---------- main: keypoints + softmax + deformable gather ----------
__global__ __launch_bounds__(256) void dfa_main_kernel(
    const float* __restrict__ iff, const float* __restrict__ anc,
    const float* __restrict__ pm, const float* __restrict__ wh,
    float* __restrict__ out){
  int n = blockIdx.x;
  int b = n / NA;
  int tid = threadIdx.x;
  int wid = tid>>5, ln = tid&31;

  __shared__ float sIF[E_DIM];
  __shared__ float sA[11];
  __shared__ float sLS[18];
  __shared__ float sKP[NPTS][3];
  __shared__ float sWgt[NCAM*WO];
  __shared__ float sGX[NSAMP], sGY[NSAMP];
  __shared__ int   sOff[NSAMP];     // base offset into g_fmt (level+image)
  __shared__ int   sWHs[NSAMP];     // Wl | (Hl<<16); 0 => skip
  __shared__ float sFused[E_DIM];

  // P1: loads
  sIF[tid] = iff[(size_t)n*E_DIM+tid];
  sFused[tid] = 0.f;
  if(tid<11) sA[tid] = anc[(size_t)n*11+tid];
  if(tid<18) sLS[tid] = g_ls[n*18+tid];
  __syncthreads();

  // P2: logits + keypoints
  #pragma unroll
  for(int idx=tid; idx<NCAM*WO; idx+=256){
    int c = idx/WO, o = idx - c*WO;
    sWgt[idx] = g_featW[(size_t)n*WO+o] + g_ceWb[(b*NCAM+c)*WO+o];
  }
  if(tid<NPTS){
    float sx = expf(sA[3]), sy2 = expf(sA[4]), sz = expf(sA[5]);
    float kx,ky,kz;
    if(tid<7){ kx=c_fix[tid][0]*sx; ky=c_fix[tid][1]*sy2; kz=c_fix[tid][2]*sz; }
    else { int i=tid-7; kx=sLS[i*3+0]*sx; ky=sLS[i*3+1]*sy2; kz=sLS[i*3+2]*sz; }
    float sn = sA[6], cs = sA[7];
    sKP[tid][0] = cs*kx - sn*ky + sA[0];
    sKP[tid][1] = sn*kx + cs*ky + sA[1];
    sKP[tid][2] = kz + sA[2];
  }
  __syncthreads();

  // P3: softmax per group (warp g)
  {
    int g = wid;
    float mx = -1e30f;
    for(int j=ln;j<SOFTN;j+=32){
      int c=j/52, k=j-c*52;
      mx = fmaxf(mx, sWgt[c*WO + k*8 + g]);
    }
    #pragma unroll
    for(int o=16;o;o>>=1) mx = fmaxf(mx, __shfl_xor_sync(0xffffffffu, mx, o));
    float sum = 0.f;
    for(int j=ln;j<SOFTN;j+=32){
      int c=j/52, k=j-c*52;
      sum += __expf(sWgt[c*WO + k*8 + g] - mx);
    }
    #pragma unroll
    for(int o=16;o;o>>=1) sum += __shfl_xor_sync(0xffffffffu, sum, o);
    float inv = 1.f/sum;
    for(int j=ln;j<SOFTN;j+=32){
      int c=j/52, k=j-c*52;
      int idx = c*WO + k*8 + g;
      sWgt[idx] = __expf(sWgt[idx] - mx) * inv;
    }
  }
  __syncthreads();

  // P4: per-sample table (312 entries; project & precompute coords)
  for(int idx=tid; idx<NSAMP; idx+=256){
    int c = idx/52, r = idx - c*52, l = r/13, p = r - l*13;
    const float* P = pm + (size_t)(b*NCAM+c)*16;
    float X = sKP[p][0], Y = sKP[p][1], Z = sKP[p][2];
    float r0 = P[0]*X + P[1]*Y + P[2]*Z  + P[3];
    float r1 = P[4]*X + P[5]*Y + P[6]*Z  + P[7];
    float r2 = P[8]*X + P[9]*Y + P[10]*Z + P[11];
    float z = fmaxf(r2, 1e-5f);
    float iwx = wh[(b*NCAM+c)*2+0], iwy = wh[(b*NCAM+c)*2+1];
    int Wl = c_lW[l], Hl = c_lH[l];
    float fW = (float)Wl, fH = (float)Hl;
    float gx = (r0/z)/iwx*fW - 0.5f;
    float gy = (r1/z)/iwy*fH - 0.5f;
    bool valid = (gx > -1.f && gx < fW && gy > -1.f && gy < fH);
    sGX[idx] = gx; sGY[idx] = gy;
    sOff[idx] = c_lOff[l] + (b*NCAM+c)*c_lStr[l];
    sWHs[idx] = valid ? (Wl | (Hl<<16)) : 0;
  }
  __syncthreads();

  // P5: sampling.  warp w owns samples s = w, w+8, ...
  // lane owns channels [8*ln..8*ln+7], all in group ln>>2 -> single weight per sample
  float acc[8];
  #pragma unroll
  for(int j=0;j<8;j++) acc[j]=0.f;
  int g = ln>>2;

  for(int s = wid; s < NSAMP; s += 8){
    int whp = sWHs[s];
    if(!whp) continue;
    int Wl = whp & 0xffff, Hl = whp >> 16;
    float gx = sGX[s], gy = sGY[s];
    float x0f = floorf(gx), y0f = floorf(gy);
    float wx1 = gx - x0f, wy1 = gy - y0f;
    float wx0 = 1.f - wx1, wy0 = 1.f - wy1;
    int x0 = (int)x0f, y0 = (int)y0f;
    bool vx0 = (x0 >= 0), vx1 = (x0+1 < Wl);
    bool vy0 = (y0 >= 0), vy1 = (y0+1 < Hl);
    const __half* imgb = g_fmt + sOff[s];
    float sv[8];
    #pragma unroll
    for(int j=0;j<8;j++) sv[j]=0.f;
    #define TAP(px, py, wt) { \
      uint4 u = *((const uint4*)(imgb + ((size_t)((py)*Wl + (px))<<8)) + ln); \
      const __half2* hp = (const __half2*)&u; \
      _Pragma("unroll") \
      for(int j=0;j<4;j++){ \
        float2 f = __half22float2(hp[j]); \
        sv[2*j]   += (wt)*f.x; \
        sv[2*j+1] += (wt)*f.y; \
      } }
    if(vy0){
      if(vx0) TAP(x0,   y0, wx0*wy0);
      if(vx1) TAP(x0+1, y0, wx1*wy0);
    }
    if(vy1){
      if(vx0) TAP(x0,   y0+1, wx0*wy1);
      if(vx1) TAP(x0+1, y0+1, wx1*wy1);
    }
    #undef TAP
    float wt = sWgt[s*8 + g];
    #pragma unroll
    for(int j=0;j<8;j++) acc[j] += wt*sv[j];
  }
  #pragma unroll
  for(int j=0;j<8;j++) atomicAdd(&sFused[8*ln+j], acc[j]);
  __syncthreads();

  g_fused[(size_t)n*E_DIM + tid] = sFused[tid];
  out[(size_t)n*512 + 256 + tid] = sIF[tid];
}

// ---------- final projection ----------
__global__ __launch_bounds__(256) void outproj_kernel(const float* __restrict__ opw,
    const float* __restrict__ opb, float* __restrict__ out){
  __shared__ float fs[32][E_DIM];
  int a0 = blockIdx.x*32;
  int tid = threadIdx.x;
  #pragma unroll 4
  for(int m=0;m<32;m++){
    int a = a0+m;
    fs[m][tid] = (a<NANCH) ? g_fused[(size_t)a*E_DIM+tid] : 0.f;
  }
  __syncthreads();
  float acc[32];
  float bias = opb[tid];
  #pragma unroll
  for(int m=0;m<32;m++) acc[m]=bias;
  for(int e=0;e<E_DIM;e++){
    float wv = opw[e*E_DIM+tid];
    #pragma unroll
    for(int m=0;m<32;m++) acc[m] += fs[m][e]*wv;
  }
  #pragma unroll
  for(int m=0;m<32;m++){
    int a = a0+m;
    if(a<NANCH) out[(size_t)a*512 + tid] = acc[m];
  }
}

// ---------- host launcher ----------
extern "C" void kernel_launch(void* const* d_in, const int* in_sizes, int n_in,
                              void* d_out, int out_size) {
  int iIF=0, iAE=2, iPM, iWH, iFM0, iFM1, iFM2, iFM3;
  int iANC=1;
  if(in_sizes[3]==192){ iPM=3; iWH=4; iFM0=5; iFM1=6; iFM2=7; iFM3=8; }
  else                { iFM0=3; iFM1=4; iFM2=5; iFM3=6; iPM=7; iWH=8; }
  int iLFW=9, iLFB=10, iC1W=11, iC1B=12, iL1G=13, iL1B=14,
      iC2W=15, iC2B=16, iL2G=17, iL2B=18, iWFW=19, iWFB=20, iOPW=21, iOPB=22;

  const float* iff  = (const float*)d_in[iIF];
  const float* anc  = (const float*)d_in[iANC];
  const float* ae   = (const float*)d_in[iAE];
  const float* pm   = (const float*)d_in[iPM];
  const float* wh   = (const float*)d_in[iWH];
  const float* fm0  = (const float*)d_in[iFM0];
  const float* fm1  = (const float*)d_in[iFM1];
  const float* fm2  = (const float*)d_in[iFM2];
  const float* fm3  = (const float*)d_in[iFM3];
  const float* lfcw = (const float*)d_in[iLFW];
  const float* lfcb = (const float*)d_in[iLFB];
  const float* c1w  = (const float*)d_in[iC1W];
  const float* c1b  = (const float*)d_in[iC1B];
  const float* l1g  = (const float*)d_in[iL1G];
  const float* l1b  = (const float*)d_in[iL1B];
  const float* c2w  = (const float*)d_in[iC2W];
  const float* c2b  = (const float*)d_in[iC2B];
  const float* l2g  = (const float*)d_in[iL2G];
  const float* l2b  = (const float*)d_in[iL2B];
  const float* wfw  = (const float*)d_in[iWFW];
  const float* wfb  = (const float*)d_in[iWFB];
  const float* opw  = (const float*)d_in[iOPW];
  const float* opb  = (const float*)d_in[iOPB];
  float* out = (float*)d_out;

  transpose_all_kernel<<<11232, 256>>>(fm0, fm1, fm2, fm3);
  ls_kernel<<<(NANCH*18 + 255)/256, 256>>>(iff, lfcw, lfcb);
  cam_embed_kernel<<<12, 256>>>(pm, c1w, c1b, l1g, l1b, c2w, c2b, l2g, l2b, wfw, wfb);
  featw_kernel<<<(NANCH+31)/32, 256>>>(iff, ae, wfw);
  dfa_main_kernel<<<NANCH, 256>>>(iff, anc, pm, wh, out);
  outproj_kernel<<<(NANCH+31)/32, 256>>>(opw, opb, out);
}

// round 5
// speedup vs baseline: 2.5532x; 1.9754x over previous
#include <cuda_runtime.h>
#include <cuda_fp16.h>
#include <math.h>
#include <stdint.h>

// Problem constants
#define E_DIM   256
#define NA      900
#define BS      2
#define NCAM    6
#define NLVL    4
#define NPTS    13
#define NG      8
#define NANCH   (BS*NA)          // 1800
#define WO      416              // G*NL*NPTS
#define NSAMP   (NCAM*NLVL*NPTS) // 312
#define SOFTN   312

// Levels: 0: 64x176  1: 32x88  2: 16x44  3: 8x22
#define FMT_TOTAL 45957120

__device__ __half g_fmt[FMT_TOTAL];
__device__ float  g_featW[NANCH*WO];
__device__ float  g_ceWb[12*WO];
__device__ float  g_ls[NANCH*18];
__device__ float  g_fused[NANCH*E_DIM];

__constant__ float c_fix[7][3] = {
  {0.f,0.f,0.f},{0.45f,0.f,0.f},{-0.45f,0.f,0.f},{0.f,0.45f,0.f},
  {0.f,-0.45f,0.f},{0.f,0.f,0.45f},{0.f,0.f,-0.45f}};

__constant__ int c_lW[4]   = {176,88,44,22};
__constant__ int c_lH[4]   = {64,32,16,8};
__constant__ int c_lOff[4] = {0,34603008,43253760,45416448};
__constant__ int c_lStr[4] = {2883584,720896,180224,45056};   // HW*256 per image

// ---------- merged vectorized transpose+convert ----------
__global__ __launch_bounds__(256) void transpose_all_kernel(
    const float* __restrict__ f0, const float* __restrict__ f1,
    const float* __restrict__ f2, const float* __restrict__ f3){
  int bid = blockIdx.x;
  int l, bl;
  if(bid < 8448){ l=0; bl=bid; }
  else if(bid < 10560){ l=1; bl=bid-8448; }
  else if(bid < 11088){ l=2; bl=bid-10560; }
  else { l=3; bl=bid-11088; }
  const float* src; int HW, thw; int dstOff;
  if(l==0){src=f0;HW=11264;thw=176;dstOff=0;}
  else if(l==1){src=f1;HW=2816;thw=44;dstOff=34603008;}
  else if(l==2){src=f2;HW=704;thw=11;dstOff=43253760;}
  else {src=f3;HW=176;thw=3;dstOff=45416448;}
  int e_t = bl & 3; int tmp = bl >> 2;
  int hw_t = tmp % thw; int img = tmp / thw;
  int e0 = e_t*64, hw0 = hw_t*64;
  const float* s = src + (size_t)img*E_DIM*HW;
  __half* d = g_fmt + dstOff + (size_t)img*HW*E_DIM;

  __shared__ float sm[64][65];
  int t = threadIdx.x;
  int col = t & 15, row0 = t >> 4;
  int hwc = hw0 + col*4;
  if(hwc < HW){
    #pragma unroll
    for(int i=0;i<4;i++){
      int r = row0 + 16*i;
      float4 v = *(const float4*)(s + (size_t)(e0+r)*HW + hwc);
      sm[r][col*4+0]=v.x; sm[r][col*4+1]=v.y; sm[r][col*4+2]=v.z; sm[r][col*4+3]=v.w;
    }
  }
  __syncthreads();
  int chunk = t & 7, hrow = t >> 3;
  #pragma unroll
  for(int i=0;i<2;i++){
    int hw = hrow + 32*i;
    if(hw0+hw < HW){
      __half2 h[4];
      #pragma unroll
      for(int j=0;j<4;j++)
        h[j] = __floats2half2_rn(sm[8*chunk+2*j][hw], sm[8*chunk+2*j+1][hw]);
      *(uint4*)(d + (size_t)(hw0+hw)*E_DIM + e0 + 8*chunk) = *(uint4*)h;
    }
  }
}

// ---------- tiled fp32 GEMM: C[M,N](ldc) = (A [+A2]) @ B [+bias] ----------
// A: M x 256 row-major. B: 256 x N row-major. tile 64x64, K-chunk 16,
// 256 threads, 4x4 micro-tile per thread.
__global__ __launch_bounds__(256) void gemm_kernel(
    const float* __restrict__ A, const float* __restrict__ A2,
    const float* __restrict__ B, const float* __restrict__ bias,
    float* __restrict__ C, int M, int N, int ldc){
  __shared__ float As[16][64];
  __shared__ float Bs[16][68];
  int m0 = blockIdx.x*64, n0 = blockIdx.y*64;
  int t = threadIdx.x;
  int tm = t>>4, tn = t&15;
  int rowA = t>>2, kvA = (t&3)<<2;
  int kkB = t>>4, nvB = (t&15)<<2;
  float acc[4][4];
  #pragma unroll
  for(int i=0;i<4;i++)
    #pragma unroll
    for(int j=0;j<4;j++) acc[i][j]=0.f;

  for(int k0=0; k0<E_DIM; k0+=16){
    float4 av = make_float4(0,0,0,0);
    int gm = m0+rowA;
    if(gm < M){
      av = *(const float4*)(A + (size_t)gm*E_DIM + k0 + kvA);
      if(A2){
        float4 a2 = *(const float4*)(A2 + (size_t)gm*E_DIM + k0 + kvA);
        av.x+=a2.x; av.y+=a2.y; av.z+=a2.z; av.w+=a2.w;
      }
    }
    float4 bv = make_float4(0,0,0,0);
    {
      int gn = n0+nvB;
      const float* bp = B + (size_t)(k0+kkB)*N + gn;
      if(gn+3 < N) bv = *(const float4*)bp;
      else {
        if(gn  <N) bv.x = bp[0];
        if(gn+1<N) bv.y = bp[1];
        if(gn+2<N) bv.z = bp[2];
      }
    }
    __syncthreads();
    As[kvA+0][rowA]=av.x; As[kvA+1][rowA]=av.y;
    As[kvA+2][rowA]=av.z; As[kvA+3][rowA]=av.w;
    *(float4*)&Bs[kkB][nvB] = bv;
    __syncthreads();
    #pragma unroll
    for(int kk=0;kk<16;kk++){
      float a[4], b[4];
      *(float4*)a = *(const float4*)&As[kk][tm*4];
      *(float4*)b = *(const float4*)&Bs[kk][tn*4];
      #pragma unroll
      for(int i=0;i<4;i++)
        #pragma unroll
        for(int j=0;j<4;j++)
          acc[i][j] += a[i]*b[j];
    }
  }
  #pragma unroll
  for(int i=0;i<4;i++){
    int gm = m0 + tm*4 + i;
    if(gm >= M) continue;
    int gn0 = n0 + tn*4;
    float* cp = C + (size_t)gm*ldc + gn0;
    #pragma unroll
    for(int j=0;j<4;j++){
      int gn = gn0 + j;
      if(gn < N) cp[j] = acc[i][j] + (bias ? bias[gn] : 0.f);
    }
  }
}

// ---------- learned scales ----------
__global__ __launch_bounds__(256) void ls_kernel(const float* __restrict__ iff,
    const float* __restrict__ lfcw, const float* __restrict__ lfcb){
  int idx = blockIdx.x*256 + threadIdx.x;
  if(idx >= NANCH*18) return;
  int a = idx/18, o = idx - 18*a;
  const float* f = iff + (size_t)a*E_DIM;
  float v = lfcb[o];
  #pragma unroll 4
  for(int e=0;e<E_DIM;e++) v += f[e]*lfcw[e*18+o];
  g_ls[idx] = 1.f/(1.f+__expf(-v)) - 0.5f;
}

// ---------- camera embed ----------
__device__ __forceinline__ float blockSum256(float v, float* red){
  int tid = threadIdx.x;
  red[tid] = v; __syncthreads();
  #pragma unroll
  for(int s=128;s>0;s>>=1){
    if(tid<s) red[tid]+=red[tid+s];
    __syncthreads();
  }
  float r = red[0]; __syncthreads();
  return r;
}

__global__ void cam_embed_kernel(const float* __restrict__ pm,
    const float* __restrict__ ce1w, const float* __restrict__ ce1b,
    const float* __restrict__ ln1g, const float* __restrict__ ln1b,
    const float* __restrict__ ce2w, const float* __restrict__ ce2b,
    const float* __restrict__ ln2g, const float* __restrict__ ln2b,
    const float* __restrict__ wfcw, const float* __restrict__ wfcb){
  int img = blockIdx.x;
  int tid = threadIdx.x;
  __shared__ float cam[12];
  __shared__ float h[E_DIM];
  __shared__ float red[E_DIM];
  if(tid<12) cam[tid] = pm[img*16 + tid];
  __syncthreads();
  float v = ce1b[tid];
  #pragma unroll
  for(int i=0;i<12;i++) v += cam[i]*ce1w[i*E_DIM+tid];
  v = fmaxf(v,0.f);
  float m = blockSum256(v, red) * (1.f/E_DIM);
  float dvar = v - m;
  float var = blockSum256(dvar*dvar, red) * (1.f/E_DIM);
  v = dvar * rsqrtf(var + 1e-5f) * ln1g[tid] + ln1b[tid];
  h[tid] = v; __syncthreads();
  float v2 = ce2b[tid];
  for(int i=0;i<E_DIM;i++) v2 += h[i]*ce2w[i*E_DIM+tid];
  v2 = fmaxf(v2,0.f);
  __syncthreads();
  float m2 = blockSum256(v2, red) * (1.f/E_DIM);
  float d2 = v2 - m2;
  float var2 = blockSum256(d2*d2, red) * (1.f/E_DIM);
  v2 = d2 * rsqrtf(var2 + 1e-5f) * ln2g[tid] + ln2b[tid];
  h[tid] = v2; __syncthreads();
  for(int o=tid;o<WO;o+=256){
    float a = wfcb[o];
    for(int e=0;e<E_DIM;e++) a += h[e]*wfcw[e*WO+o];
    g_ceWb[img*WO+o] = a;
  }
}

// ---------- main: keypoints + softmax + deformable gather ----------
__global__ __launch_bounds__(256) void dfa_main_kernel(
    const float* __restrict__ iff, const float* __restrict__ anc,
    const float* __restrict__ pm, const float* __restrict__ wh,
    float* __restrict__ out){
  int n = blockIdx.x;
  int b = n / NA;
  int tid = threadIdx.x;
  int wid = tid>>5, ln = tid&31;

  __shared__ float sIF[E_DIM];
  __shared__ float sA[11];
  __shared__ float sLS[18];
  __shared__ float sKP[NPTS][3];
  __shared__ float sWgt[NCAM*WO];
  __shared__ float sGX[NSAMP], sGY[NSAMP];
  __shared__ int   sOff[NSAMP];
  __shared__ int   sWHs[NSAMP];
  __shared__ float sFused[E_DIM];

  sIF[tid] = iff[(size_t)n*E_DIM+tid];
  sFused[tid] = 0.f;
  if(tid<11) sA[tid] = anc[(size_t)n*11+tid];
  if(tid<18) sLS[tid] = g_ls[n*18+tid];
  __syncthreads();

  #pragma unroll
  for(int idx=tid; idx<NCAM*WO; idx+=256){
    int c = idx/WO, o = idx - c*WO;
    sWgt[idx] = g_featW[(size_t)n*WO+o] + g_ceWb[(b*NCAM+c)*WO+o];
  }
  if(tid<NPTS){
    float sx = expf(sA[3]), sy2 = expf(sA[4]), sz = expf(sA[5]);
    float kx,ky,kz;
    if(tid<7){ kx=c_fix[tid][0]*sx; ky=c_fix[tid][1]*sy2; kz=c_fix[tid][2]*sz; }
    else { int i=tid-7; kx=sLS[i*3+0]*sx; ky=sLS[i*3+1]*sy2; kz=sLS[i*3+2]*sz; }
    float sn = sA[6], cs = sA[7];
    sKP[tid][0] = cs*kx - sn*ky + sA[0];
    sKP[tid][1] = sn*kx + cs*ky + sA[1];
    sKP[tid][2] = kz + sA[2];
  }
  __syncthreads();

  {
    int g = wid;
    float mx = -1e30f;
    for(int j=ln;j<SOFTN;j+=32){
      int c=j/52, k=j-c*52;
      mx = fmaxf(mx, sWgt[c*WO + k*8 + g]);
    }
    #pragma unroll
    for(int o=16;o;o>>=1) mx = fmaxf(mx, __shfl_xor_sync(0xffffffffu, mx, o));
    float sum = 0.f;
    for(int j=ln;j<SOFTN;j+=32){
      int c=j/52, k=j-c*52;
      sum += __expf(sWgt[c*WO + k*8 + g] - mx);
    }
    #pragma unroll
    for(int o=16;o;o>>=1) sum += __shfl_xor_sync(0xffffffffu, sum, o);
    float inv = 1.f/sum;
    for(int j=ln;j<SOFTN;j+=32){
      int c=j/52, k=j-c*52;
      int idx = c*WO + k*8 + g;
      sWgt[idx] = __expf(sWgt[idx] - mx) * inv;
    }
  }
  __syncthreads();

  for(int idx=tid; idx<NSAMP; idx+=256){
    int c = idx/52, r = idx - c*52, l = r/13, p = r - l*13;
    const float* P = pm + (size_t)(b*NCAM+c)*16;
    float X = sKP[p][0], Y = sKP[p][1], Z = sKP[p][2];
    float r0 = P[0]*X + P[1]*Y + P[2]*Z  + P[3];
    float r1 = P[4]*X + P[5]*Y + P[6]*Z  + P[7];
    float r2 = P[8]*X + P[9]*Y + P[10]*Z + P[11];
    float z = fmaxf(r2, 1e-5f);
    float iwx = wh[(b*NCAM+c)*2+0], iwy = wh[(b*NCAM+c)*2+1];
    int Wl = c_lW[l], Hl = c_lH[l];
    float fW = (float)Wl, fH = (float)Hl;
    float gx = (r0/z)/iwx*fW - 0.5f;
    float gy = (r1/z)/iwy*fH - 0.5f;
    bool valid = (gx > -1.f && gx < fW && gy > -1.f && gy < fH);
    sGX[idx] = gx; sGY[idx] = gy;
    sOff[idx] = c_lOff[l] + (b*NCAM+c)*c_lStr[l];
    sWHs[idx] = valid ? (Wl | (Hl<<16)) : 0;
  }
  __syncthreads();

  float acc[8];
  #pragma unroll
  for(int j=0;j<8;j++) acc[j]=0.f;
  int g = ln>>2;

  for(int s = wid; s < NSAMP; s += 8){
    int whp = sWHs[s];
    if(!whp) continue;
    int Wl = whp & 0xffff, Hl = whp >> 16;
    float gx = sGX[s], gy = sGY[s];
    float x0f = floorf(gx), y0f = floorf(gy);
    float wx1 = gx - x0f, wy1 = gy - y0f;
    float wx0 = 1.f - wx1, wy0 = 1.f - wy1;
    int x0 = (int)x0f, y0 = (int)y0f;
    bool vx0 = (x0 >= 0), vx1 = (x0+1 < Wl);
    bool vy0 = (y0 >= 0), vy1 = (y0+1 < Hl);
    const __half* imgb = g_fmt + sOff[s];
    float sv[8];
    #pragma unroll
    for(int j=0;j<8;j++) sv[j]=0.f;
    #define TAP(px, py, wt) { \
      uint4 u = *((const uint4*)(imgb + ((size_t)((py)*Wl + (px))<<8)) + ln); \
      const __half2* hp = (const __half2*)&u; \
      _Pragma("unroll") \
      for(int j=0;j<4;j++){ \
        float2 f = __half22float2(hp[j]); \
        sv[2*j]   += (wt)*f.x; \
        sv[2*j+1] += (wt)*f.y; \
      } }
    if(vy0){
      if(vx0) TAP(x0,   y0, wx0*wy0);
      if(vx1) TAP(x0+1, y0, wx1*wy0);
    }
    if(vy1){
      if(vx0) TAP(x0,   y0+1, wx0*wy1);
      if(vx1) TAP(x0+1, y0+1, wx1*wy1);
    }
    #undef TAP
    float wt = sWgt[s*8 + g];
    #pragma unroll
    for(int j=0;j<8;j++) acc[j] += wt*sv[j];
  }
  #pragma unroll
  for(int j=0;j<8;j++) atomicAdd(&sFused[8*ln+j], acc[j]);
  __syncthreads();

  g_fused[(size_t)n*E_DIM + tid] = sFused[tid];
  out[(size_t)n*512 + 256 + tid] = sIF[tid];
}

// ---------- host launcher ----------
extern "C" void kernel_launch(void* const* d_in, const int* in_sizes, int n_in,
                              void* d_out, int out_size) {
  int iIF=0, iAE=2, iPM, iWH, iFM0, iFM1, iFM2, iFM3;
  int iANC=1;
  if(in_sizes[3]==192){ iPM=3; iWH=4; iFM0=5; iFM1=6; iFM2=7; iFM3=8; }
  else                { iFM0=3; iFM1=4; iFM2=5; iFM3=6; iPM=7; iWH=8; }
  int iLFW=9, iLFB=10, iC1W=11, iC1B=12, iL1G=13, iL1B=14,
      iC2W=15, iC2B=16, iL2G=17, iL2B=18, iWFW=19, iWFB=20, iOPW=21, iOPB=22;

  const float* iff  = (const float*)d_in[iIF];
  const float* anc  = (const float*)d_in[iANC];
  const float* ae   = (const float*)d_in[iAE];
  const float* pm   = (const float*)d_in[iPM];
  const float* wh   = (const float*)d_in[iWH];
  const float* fm0  = (const float*)d_in[iFM0];
  const float* fm1  = (const float*)d_in[iFM1];
  const float* fm2  = (const float*)d_in[iFM2];
  const float* fm3  = (const float*)d_in[iFM3];
  const float* lfcw = (const float*)d_in[iLFW];
  const float* lfcb = (const float*)d_in[iLFB];
  const float* c1w  = (const float*)d_in[iC1W];
  const float* c1b  = (const float*)d_in[iC1B];
  const float* l1g  = (const float*)d_in[iL1G];
  const float* l1b  = (const float*)d_in[iL1B];
  const float* c2w  = (const float*)d_in[iC2W];
  const float* c2b  = (const float*)d_in[iC2B];
  const float* l2g  = (const float*)d_in[iL2G];
  const float* l2b  = (const float*)d_in[iL2B];
  const float* wfw  = (const float*)d_in[iWFW];
  const float* wfb  = (const float*)d_in[iWFB];
  const float* opw  = (const float*)d_in[iOPW];
  const float* opb  = (const float*)d_in[iOPB];
  float* out = (float*)d_out;

  // device pointers for scratch (valid to take address of __device__ vars via symbol in same TU)
  float* p_featW; cudaGetSymbolAddress((void**)&p_featW, g_featW);
  float* p_fused; cudaGetSymbolAddress((void**)&p_fused, g_fused);

  transpose_all_kernel<<<11232, 256>>>(fm0, fm1, fm2, fm3);
  ls_kernel<<<(NANCH*18 + 255)/256, 256>>>(iff, lfcw, lfcb);
  cam_embed_kernel<<<12, 256>>>(pm, c1w, c1b, l1g, l1b, c2w, c2b, l2g, l2b, wfw, wfb);
  // featW = (iff + ae) @ wfc_w        (M=1800, N=416, ldc=416, no bias)
  gemm_kernel<<<dim3(29,7), 256>>>(iff, ae, wfw, nullptr, p_featW, NANCH, WO, WO);
  dfa_main_kernel<<<NANCH, 256>>>(iff, anc, pm, wh, out);
  // out[:, :256] = g_fused @ op_w + op_b   (M=1800, N=256, ldc=512)
  gemm_kernel<<<dim3(29,4), 256>>>(p_fused, nullptr, opw, opb, out, NANCH, E_DIM, 512);
}

// round 6
// speedup vs baseline: 2.6196x; 1.0260x over previous
#include <cuda_runtime.h>
#include <cuda_fp16.h>
#include <math.h>
#include <stdint.h>

// Problem constants
#define E_DIM   256
#define NA      900
#define BS      2
#define NCAM    6
#define NLVL    4
#define NPTS    13
#define NG      8
#define NANCH   (BS*NA)          // 1800
#define WO      416              // G*NL*NPTS
#define NSAMP   (NCAM*NLVL*NPTS) // 312
#define SOFTN   312

// Levels: 0: 64x176  1: 32x88  2: 16x44  3: 8x22
#define FMT_TOTAL 45957120

__device__ __half g_fmt[FMT_TOTAL];
__device__ float  g_featW[NANCH*WO];
__device__ float  g_ceWb[12*WO];
__device__ float  g_ls[NANCH*18];
__device__ float  g_fused[NANCH*E_DIM];

__constant__ float c_fix[7][3] = {
  {0.f,0.f,0.f},{0.45f,0.f,0.f},{-0.45f,0.f,0.f},{0.f,0.45f,0.f},
  {0.f,-0.45f,0.f},{0.f,0.f,0.45f},{0.f,0.f,-0.45f}};

__constant__ int c_lW[4]   = {176,88,44,22};
__constant__ int c_lH[4]   = {64,32,16,8};
__constant__ int c_lOff[4] = {0,34603008,43253760,45416448};
__constant__ int c_lStr[4] = {2883584,720896,180224,45056};   // HW*256 per image

// ---------- merged vectorized transpose+convert ----------
__global__ __launch_bounds__(256) void transpose_all_kernel(
    const float* __restrict__ f0, const float* __restrict__ f1,
    const float* __restrict__ f2, const float* __restrict__ f3){
  int bid = blockIdx.x;
  int l, bl;
  if(bid < 8448){ l=0; bl=bid; }
  else if(bid < 10560){ l=1; bl=bid-8448; }
  else if(bid < 11088){ l=2; bl=bid-10560; }
  else { l=3; bl=bid-11088; }
  const float* src; int HW, thw; int dstOff;
  if(l==0){src=f0;HW=11264;thw=176;dstOff=0;}
  else if(l==1){src=f1;HW=2816;thw=44;dstOff=34603008;}
  else if(l==2){src=f2;HW=704;thw=11;dstOff=43253760;}
  else {src=f3;HW=176;thw=3;dstOff=45416448;}
  int e_t = bl & 3; int tmp = bl >> 2;
  int hw_t = tmp % thw; int img = tmp / thw;
  int e0 = e_t*64, hw0 = hw_t*64;
  const float* s = src + (size_t)img*E_DIM*HW;
  __half* d = g_fmt + dstOff + (size_t)img*HW*E_DIM;

  __shared__ float sm[64][65];
  int t = threadIdx.x;
  int col = t & 15, row0 = t >> 4;
  int hwc = hw0 + col*4;
  if(hwc < HW){
    #pragma unroll
    for(int i=0;i<4;i++){
      int r = row0 + 16*i;
      float4 v = *(const float4*)(s + (size_t)(e0+r)*HW + hwc);
      sm[r][col*4+0]=v.x; sm[r][col*4+1]=v.y; sm[r][col*4+2]=v.z; sm[r][col*4+3]=v.w;
    }
  }
  __syncthreads();
  int chunk = t & 7, hrow = t >> 3;
  #pragma unroll
  for(int i=0;i<2;i++){
    int hw = hrow + 32*i;
    if(hw0+hw < HW){
      __half2 h[4];
      #pragma unroll
      for(int j=0;j<4;j++)
        h[j] = __floats2half2_rn(sm[8*chunk+2*j][hw], sm[8*chunk+2*j+1][hw]);
      *(uint4*)(d + (size_t)(hw0+hw)*E_DIM + e0 + 8*chunk) = *(uint4*)h;
    }
  }
}

// ---------- tiled fp32 GEMM with register prefetch ----------
// C[M,N](ldc) = (A [+A2]) @ B [+bias].  tile 64x64, K-chunk 16, 4x4 micro-tile.
__global__ __launch_bounds__(256) void gemm_kernel(
    const float* __restrict__ A, const float* __restrict__ A2,
    const float* __restrict__ B, const float* __restrict__ bias,
    float* __restrict__ C, int M, int N, int ldc){
  __shared__ float As[16][64];
  __shared__ float Bs[16][68];
  int m0 = blockIdx.x*64, n0 = blockIdx.y*64;
  int t = threadIdx.x;
  int tm = t>>4, tn = t&15;
  int rowA = t>>2, kvA = (t&3)<<2;
  int kkB = t>>4, nvB = (t&15)<<2;
  int gm = m0+rowA;
  int gn = n0+nvB;
  float acc[4][4];
  #pragma unroll
  for(int i=0;i<4;i++)
    #pragma unroll
    for(int j=0;j<4;j++) acc[i][j]=0.f;

  const float* Ap  = (gm < M) ? A  + (size_t)gm*E_DIM + kvA : nullptr;
  const float* A2p = (A2 && gm < M) ? A2 + (size_t)gm*E_DIM + kvA : nullptr;

  // prefetch chunk 0
  float4 av = make_float4(0,0,0,0), bv = make_float4(0,0,0,0);
  if(Ap){
    av = *(const float4*)(Ap);
    if(A2p){ float4 a2 = *(const float4*)(A2p); av.x+=a2.x; av.y+=a2.y; av.z+=a2.z; av.w+=a2.w; }
  }
  {
    const float* bp = B + (size_t)kkB*N + gn;
    if(gn+3 < N) bv = *(const float4*)bp;
    else { if(gn<N) bv.x=bp[0]; if(gn+1<N) bv.y=bp[1]; if(gn+2<N) bv.z=bp[2]; }
  }

  for(int k0=0; k0<E_DIM; k0+=16){
    __syncthreads();
    As[kvA+0][rowA]=av.x; As[kvA+1][rowA]=av.y;
    As[kvA+2][rowA]=av.z; As[kvA+3][rowA]=av.w;
    *(float4*)&Bs[kkB][nvB] = bv;
    __syncthreads();
    if(k0+16 < E_DIM){
      av = make_float4(0,0,0,0);
      if(Ap){
        av = *(const float4*)(Ap + k0 + 16);
        if(A2p){ float4 a2 = *(const float4*)(A2p + k0 + 16); av.x+=a2.x; av.y+=a2.y; av.z+=a2.z; av.w+=a2.w; }
      }
      const float* bp = B + (size_t)(k0+16+kkB)*N + gn;
      if(gn+3 < N) bv = *(const float4*)bp;
      else { bv=make_float4(0,0,0,0); if(gn<N) bv.x=bp[0]; if(gn+1<N) bv.y=bp[1]; if(gn+2<N) bv.z=bp[2]; }
    }
    #pragma unroll
    for(int kk=0;kk<16;kk++){
      float a[4], b[4];
      *(float4*)a = *(const float4*)&As[kk][tm*4];
      *(float4*)b = *(const float4*)&Bs[kk][tn*4];
      #pragma unroll
      for(int i=0;i<4;i++)
        #pragma unroll
        for(int j=0;j<4;j++)
          acc[i][j] += a[i]*b[j];
    }
  }
  #pragma unroll
  for(int i=0;i<4;i++){
    int gmo = m0 + tm*4 + i;
    if(gmo >= M) continue;
    int gn0 = n0 + tn*4;
    float* cp = C + (size_t)gmo*ldc + gn0;
    #pragma unroll
    for(int j=0;j<4;j++){
      int gno = gn0 + j;
      if(gno < N) cp[j] = acc[i][j] + (bias ? bias[gno] : 0.f);
    }
  }
}

// ---------- learned scales ----------
__global__ __launch_bounds__(256) void ls_kernel(const float* __restrict__ iff,
    const float* __restrict__ lfcw, const float* __restrict__ lfcb){
  int idx = blockIdx.x*256 + threadIdx.x;
  if(idx >= NANCH*18) return;
  int a = idx/18, o = idx - 18*a;
  const float* f = iff + (size_t)a*E_DIM;
  float v = lfcb[o];
  #pragma unroll 4
  for(int e=0;e<E_DIM;e++) v += f[e]*lfcw[e*18+o];
  g_ls[idx] = 1.f/(1.f+__expf(-v)) - 0.5f;
}

// ---------- camera embed ----------
__device__ __forceinline__ float blockSum256(float v, float* red){
  int tid = threadIdx.x;
  red[tid] = v; __syncthreads();
  #pragma unroll
  for(int s=128;s>0;s>>=1){
    if(tid<s) red[tid]+=red[tid+s];
    __syncthreads();
  }
  float r = red[0]; __syncthreads();
  return r;
}

__global__ void cam_embed_kernel(const float* __restrict__ pm,
    const float* __restrict__ ce1w, const float* __restrict__ ce1b,
    const float* __restrict__ ln1g, const float* __restrict__ ln1b,
    const float* __restrict__ ce2w, const float* __restrict__ ce2b,
    const float* __restrict__ ln2g, const float* __restrict__ ln2b,
    const float* __restrict__ wfcw, const float* __restrict__ wfcb){
  int img = blockIdx.x;
  int tid = threadIdx.x;
  __shared__ float cam[12];
  __shared__ float h[E_DIM];
  __shared__ float red[E_DIM];
  if(tid<12) cam[tid] = pm[img*16 + tid];
  __syncthreads();
  float v = ce1b[tid];
  #pragma unroll
  for(int i=0;i<12;i++) v += cam[i]*ce1w[i*E_DIM+tid];
  v = fmaxf(v,0.f);
  float m = blockSum256(v, red) * (1.f/E_DIM);
  float dvar = v - m;
  float var = blockSum256(dvar*dvar, red) * (1.f/E_DIM);
  v = dvar * rsqrtf(var + 1e-5f) * ln1g[tid] + ln1b[tid];
  h[tid] = v; __syncthreads();
  float v2 = ce2b[tid];
  for(int i=0;i<E_DIM;i++) v2 += h[i]*ce2w[i*E_DIM+tid];
  v2 = fmaxf(v2,0.f);
  __syncthreads();
  float m2 = blockSum256(v2, red) * (1.f/E_DIM);
  float d2 = v2 - m2;
  float var2 = blockSum256(d2*d2, red) * (1.f/E_DIM);
  v2 = d2 * rsqrtf(var2 + 1e-5f) * ln2g[tid] + ln2b[tid];
  h[tid] = v2; __syncthreads();
  for(int o=tid;o<WO;o+=256){
    float a = wfcb[o];
    for(int e=0;e<E_DIM;e++) a += h[e]*wfcw[e*WO+o];
    g_ceWb[img*WO+o] = a;
  }
}

// ---------- main: keypoints + softmax + compacted deformable gather ----------
__global__ __launch_bounds__(256) void dfa_main_kernel(
    const float* __restrict__ iff, const float* __restrict__ anc,
    const float* __restrict__ pm, const float* __restrict__ wh,
    float* __restrict__ out){
  int n = blockIdx.x;
  int b = n / NA;
  int tid = threadIdx.x;
  int wid = tid>>5, ln = tid&31;

  __shared__ float sIF[E_DIM];
  __shared__ float sA[11];
  __shared__ float sLS[18];
  __shared__ float sKP[NPTS][3];
  __shared__ float sWgt[NCAM*WO];
  __shared__ float sGX[NSAMP], sGY[NSAMP];
  __shared__ int   sOff[NSAMP];
  __shared__ int   sWHs[NSAMP];
  __shared__ short sSid[NSAMP];
  __shared__ int   sNV;
  __shared__ float sFused[E_DIM];

  sIF[tid] = iff[(size_t)n*E_DIM+tid];
  sFused[tid] = 0.f;
  if(tid==0) sNV = 0;
  if(tid<11) sA[tid] = anc[(size_t)n*11+tid];
  if(tid<18) sLS[tid] = g_ls[n*18+tid];
  __syncthreads();

  #pragma unroll
  for(int idx=tid; idx<NCAM*WO; idx+=256){
    int c = idx/WO, o = idx - c*WO;
    sWgt[idx] = g_featW[(size_t)n*WO+o] + g_ceWb[(b*NCAM+c)*WO+o];
  }
  if(tid<NPTS){
    float sx = expf(sA[3]), sy2 = expf(sA[4]), sz = expf(sA[5]);
    float kx,ky,kz;
    if(tid<7){ kx=c_fix[tid][0]*sx; ky=c_fix[tid][1]*sy2; kz=c_fix[tid][2]*sz; }
    else { int i=tid-7; kx=sLS[i*3+0]*sx; ky=sLS[i*3+1]*sy2; kz=sLS[i*3+2]*sz; }
    float sn = sA[6], cs = sA[7];
    sKP[tid][0] = cs*kx - sn*ky + sA[0];
    sKP[tid][1] = sn*kx + cs*ky + sA[1];
    sKP[tid][2] = kz + sA[2];
  }
  __syncthreads();

  // softmax per group (warp g)
  {
    int g = wid;
    float mx = -1e30f;
    for(int j=ln;j<SOFTN;j+=32){
      int c=j/52, k=j-c*52;
      mx = fmaxf(mx, sWgt[c*WO + k*8 + g]);
    }
    #pragma unroll
    for(int o=16;o;o>>=1) mx = fmaxf(mx, __shfl_xor_sync(0xffffffffu, mx, o));
    float sum = 0.f;
    for(int j=ln;j<SOFTN;j+=32){
      int c=j/52, k=j-c*52;
      sum += __expf(sWgt[c*WO + k*8 + g] - mx);
    }
    #pragma unroll
    for(int o=16;o;o>>=1) sum += __shfl_xor_sync(0xffffffffu, sum, o);
    float inv = 1.f/sum;
    for(int j=ln;j<SOFTN;j+=32){
      int c=j/52, k=j-c*52;
      int idx = c*WO + k*8 + g;
      sWgt[idx] = __expf(sWgt[idx] - mx) * inv;
    }
  }

  // per-sample projection table + valid compaction
  for(int idx=tid; idx<NSAMP; idx+=256){
    int c = idx/52, r = idx - c*52, l = r/13, p = r - l*13;
    const float* P = pm + (size_t)(b*NCAM+c)*16;
    float X = sKP[p][0], Y = sKP[p][1], Z = sKP[p][2];
    float r0 = P[0]*X + P[1]*Y + P[2]*Z  + P[3];
    float r1 = P[4]*X + P[5]*Y + P[6]*Z  + P[7];
    float r2 = P[8]*X + P[9]*Y + P[10]*Z + P[11];
    float z = fmaxf(r2, 1e-5f);
    float iwx = wh[(b*NCAM+c)*2+0], iwy = wh[(b*NCAM+c)*2+1];
    int Wl = c_lW[l], Hl = c_lH[l];
    float fW = (float)Wl, fH = (float)Hl;
    float gx = (r0/z)/iwx*fW - 0.5f;
    float gy = (r1/z)/iwy*fH - 0.5f;
    sGX[idx] = gx; sGY[idx] = gy;
    sOff[idx] = c_lOff[l] + (b*NCAM+c)*c_lStr[l];
    sWHs[idx] = Wl | (Hl<<16);
    if(gx > -1.f && gx < fW && gy > -1.f && gy < fH){
      int pos = atomicAdd(&sNV, 1);
      sSid[pos] = (short)idx;
    }
  }
  __syncthreads();

  // sampling over compacted valid list
  float acc[8];
  #pragma unroll
  for(int j=0;j<8;j++) acc[j]=0.f;
  int g = ln>>2;
  int nv = sNV;

  for(int i = wid; i < nv; i += 8){
    int s = sSid[i];
    int whp = sWHs[s];
    int Wl = whp & 0xffff, Hl = whp >> 16;
    float gx = sGX[s], gy = sGY[s];
    float x0f = floorf(gx), y0f = floorf(gy);
    float wx1 = gx - x0f, wy1 = gy - y0f;
    float wx0 = 1.f - wx1, wy0 = 1.f - wy1;
    int x0 = (int)x0f, y0 = (int)y0f;
    bool vx0 = (x0 >= 0), vx1 = (x0+1 < Wl);
    bool vy0 = (y0 >= 0), vy1 = (y0+1 < Hl);
    const __half* imgb = g_fmt + sOff[s];
    float sv[8];
    #pragma unroll
    for(int j=0;j<8;j++) sv[j]=0.f;
    #define TAP(px, py, wt) { \
      uint4 u = *((const uint4*)(imgb + ((size_t)((py)*Wl + (px))<<8)) + ln); \
      const __half2* hp = (const __half2*)&u; \
      _Pragma("unroll") \
      for(int j=0;j<4;j++){ \
        float2 f = __half22float2(hp[j]); \
        sv[2*j]   += (wt)*f.x; \
        sv[2*j+1] += (wt)*f.y; \
      } }
    if(vy0){
      if(vx0) TAP(x0,   y0, wx0*wy0);
      if(vx1) TAP(x0+1, y0, wx1*wy0);
    }
    if(vy1){
      if(vx0) TAP(x0,   y0+1, wx0*wy1);
      if(vx1) TAP(x0+1, y0+1, wx1*wy1);
    }
    #undef TAP
    float wt = sWgt[s*8 + g];
    #pragma unroll
    for(int j=0;j<8;j++) acc[j] += wt*sv[j];
  }
  #pragma unroll
  for(int j=0;j<8;j++) atomicAdd(&sFused[8*ln+j], acc[j]);
  __syncthreads();

  g_fused[(size_t)n*E_DIM + tid] = sFused[tid];
  out[(size_t)n*512 + 256 + tid] = sIF[tid];
}

// ---------- host launcher ----------
extern "C" void kernel_launch(void* const* d_in, const int* in_sizes, int n_in,
                              void* d_out, int out_size) {
  int iIF=0, iAE=2, iPM, iWH, iFM0, iFM1, iFM2, iFM3;
  int iANC=1;
  if(in_sizes[3]==192){ iPM=3; iWH=4; iFM0=5; iFM1=6; iFM2=7; iFM3=8; }
  else                { iFM0=3; iFM1=4; iFM2=5; iFM3=6; iPM=7; iWH=8; }
  int iLFW=9, iLFB=10, iC1W=11, iC1B=12, iL1G=13, iL1B=14,
      iC2W=15, iC2B=16, iL2G=17, iL2B=18, iWFW=19, iWFB=20, iOPW=21, iOPB=22;

  const float* iff  = (const float*)d_in[iIF];
  const float* anc  = (const float*)d_in[iANC];
  const float* ae   = (const float*)d_in[iAE];
  const float* pm   = (const float*)d_in[iPM];
  const float* wh   = (const float*)d_in[iWH];
  const float* fm0  = (const float*)d_in[iFM0];
  const float* fm1  = (const float*)d_in[iFM1];
  const float* fm2  = (const float*)d_in[iFM2];
  const float* fm3  = (const float*)d_in[iFM3];
  const float* lfcw = (const float*)d_in[iLFW];
  const float* lfcb = (const float*)d_in[iLFB];
  const float* c1w  = (const float*)d_in[iC1W];
  const float* c1b  = (const float*)d_in[iC1B];
  const float* l1g  = (const float*)d_in[iL1G];
  const float* l1b  = (const float*)d_in[iL1B];
  const float* c2w  = (const float*)d_in[iC2W];
  const float* c2b  = (const float*)d_in[iC2B];
  const float* l2g  = (const float*)d_in[iL2G];
  const float* l2b  = (const float*)d_in[iL2B];
  const float* wfw  = (const float*)d_in[iWFW];
  const float* wfb  = (const float*)d_in[iWFB];
  const float* opw  = (const float*)d_in[iOPW];
  const float* opb  = (const float*)d_in[iOPB];
  float* out = (float*)d_out;

  float* p_featW; cudaGetSymbolAddress((void**)&p_featW, g_featW);
  float* p_fused; cudaGetSymbolAddress((void**)&p_fused, g_fused);

  // one-time infra (created on the first, non-captured correctness call)
  static cudaStream_t s2 = nullptr;
  static cudaEvent_t evFork = nullptr, evJoin = nullptr;
  if(s2 == nullptr){
    cudaStreamCreateWithFlags(&s2, cudaStreamNonBlocking);
    cudaEventCreateWithFlags(&evFork, cudaEventDisableTiming);
    cudaEventCreateWithFlags(&evJoin, cudaEventDisableTiming);
  }

  // fork: weight-side kernels on s2, transpose on the main stream
  cudaEventRecord(evFork, 0);
  cudaStreamWaitEvent(s2, evFork, 0);

  transpose_all_kernel<<<11232, 256>>>(fm0, fm1, fm2, fm3);

  ls_kernel<<<(NANCH*18 + 255)/256, 256, 0, s2>>>(iff, lfcw, lfcb);
  cam_embed_kernel<<<12, 256, 0, s2>>>(pm, c1w, c1b, l1g, l1b, c2w, c2b, l2g, l2b, wfw, wfb);
  gemm_kernel<<<dim3(29,7), 256, 0, s2>>>(iff, ae, wfw, nullptr, p_featW, NANCH, WO, WO);

  // join
  cudaEventRecord(evJoin, s2);
  cudaStreamWaitEvent(0, evJoin, 0);

  dfa_main_kernel<<<NANCH, 256>>>(iff, anc, pm, wh, out);
  gemm_kernel<<<dim3(29,4), 256>>>(p_fused, nullptr, opw, opb, out, NANCH, E_DIM, 512);
}